// round 1
// baseline (speedup 1.0000x reference)
#include <cuda_runtime.h>
#include <math.h>

// Dims (CLEVR-scale, fixed)
#define B_   128
#define N_   36
#define DF_  512
#define DE_  256
#define DV_  512
#define H_   256
#define NC_  28
#define L_   5
#define ROWS_PER_B (N_*N_)          // 1296
#define NODE_ROWS  (B_*N_)          // 4608
#define SCALE_ 0.04419417382415922f // 1/sqrt(512)

// ------------------------- device scratch (no cudaMalloc allowed) -----------
__device__ float g_hn[NODE_ROWS * H_];       // relu(node@W_n1+b_n1)   4.7 MB
__device__ float g_q[B_ * 4 * DV_];          // q[b][l][d], l=0..3     1 MB
__device__ float g_u3[B_ * H_];
__device__ float g_u1[B_ * H_];
__device__ float g_v [B_ * H_];
__device__ float g_c3[B_];
__device__ float g_c1[B_];
__device__ float g_ce[B_];
__device__ float g_a1  [NODE_ROWS];          // sigmoid(nf.q3 * scale)
__device__ float g_sig1[NODE_ROWS];          // sigmoid(nf.q1 * scale)
__device__ float g_weit[B_ * ROWS_PER_B];    // sigmoid(ef.q2 * scale) 663 KB
__device__ float g_ph[B_ * H_];
__device__ float g_S [B_];

__device__ __forceinline__ float sigmoidf_(float x) { return 1.0f / (1.0f + expf(-x)); }

// ------------------------- K1: gather q = word_emb[program_inputs] ----------
__global__ void gather_q_kernel(const float* __restrict__ word_emb,
                                const int* __restrict__ prog_in) {
    int idx = blockIdx.x * 256 + threadIdx.x;       // B*4*512 = 262144 total
    int d = idx & (DV_ - 1);
    int l = (idx >> 9) & 3;
    int b = idx >> 11;
    int w = prog_in[b * L_ + l];
    g_q[idx] = word_emb[(size_t)w * DV_ + d];
}

// ------------------------- K2: per-batch projections u3,u1,v and scalars ----
__global__ void proj_kernel(const float* __restrict__ Wn2, const float* __restrict__ bn2,
                            const float* __restrict__ We2, const float* __restrict__ be2) {
    int b = blockIdx.x;
    int which = blockIdx.y;                   // 0->u3 (q3), 1->u1 (q1), 2->v (q2)
    const float* W; const float* bias; const float* q; float* u; float* cptr;
    if (which == 0)      { W = Wn2; bias = bn2; q = g_q + (b*4 + 3)*DV_; u = g_u3 + b*H_; cptr = g_c3 + b; }
    else if (which == 1) { W = Wn2; bias = bn2; q = g_q + (b*4 + 1)*DV_; u = g_u1 + b*H_; cptr = g_c1 + b; }
    else                 { W = We2; bias = be2; q = g_q + (b*4 + 2)*DV_; u = g_v  + b*H_; cptr = g_ce + b; }

    __shared__ float qs[DV_];
    __shared__ float red[256];
    int tid = threadIdx.x;
    qs[tid]       = q[tid];
    qs[tid + 256] = q[tid + 256];
    __syncthreads();

    int warp = tid >> 5, lane = tid & 31;
    for (int h = warp; h < H_; h += 8) {
        float acc = 0.f;
        const float* Wr = W + (size_t)h * DV_;
        #pragma unroll
        for (int t = 0; t < 16; t++) { int d = lane + t*32; acc += Wr[d] * qs[d]; }
        #pragma unroll
        for (int o = 16; o > 0; o >>= 1) acc += __shfl_xor_sync(0xffffffffu, acc, o);
        if (lane == 0) u[h] = acc;
    }
    // scalar c = bias . q
    red[tid] = bias[tid] * qs[tid] + bias[tid + 256] * qs[tid + 256];
    __syncthreads();
    for (int o = 128; o > 0; o >>= 1) { if (tid < o) red[tid] += red[tid + o]; __syncthreads(); }
    if (tid == 0) *cptr = red[0];
}

// ------------------------- K3: hn = relu(node @ W_n1 + b_n1) ----------------
// M=4608 K=512 N=256. BM=64 (R=4), BN=128, BK=32. grid (72, 2), 256 threads.
__global__ __launch_bounds__(256) void node_mlp1_kernel(
        const float* __restrict__ node, const float* __restrict__ Wn1,
        const float* __restrict__ bn1) {
    const int row0 = blockIdx.x * 64;
    const int n0   = blockIdx.y * 128;
    const int tid  = threadIdx.x;
    const int tx = tid & 15, ty = tid >> 4;

    __shared__ float Es[32][65];
    __shared__ float Ws[32][128];

    float acc[4][8];
    #pragma unroll
    for (int r = 0; r < 4; r++)
        #pragma unroll
        for (int c = 0; c < 8; c++) acc[r][c] = 0.f;

    for (int k0 = 0; k0 < DF_; k0 += 32) {
        // E tile 64x32 = 512 float4, 2 per thread (transposed into smem)
        #pragma unroll
        for (int t = 0; t < 2; t++) {
            int i4 = tid + t*256;
            int r = i4 >> 3, c4 = i4 & 7;
            float4 e = *(const float4*)(node + (size_t)(row0 + r) * DF_ + k0 + c4*4);
            Es[c4*4+0][r] = e.x; Es[c4*4+1][r] = e.y; Es[c4*4+2][r] = e.z; Es[c4*4+3][r] = e.w;
        }
        // W tile 32x128 = 1024 float4, 4 per thread
        #pragma unroll
        for (int t = 0; t < 4; t++) {
            int i4 = tid + t*256;
            int r = i4 >> 5, c4 = i4 & 31;
            *(float4*)(&Ws[r][c4*4]) = *(const float4*)(Wn1 + (size_t)(k0 + r) * H_ + n0 + c4*4);
        }
        __syncthreads();
        #pragma unroll
        for (int kk = 0; kk < 32; kk++) {
            float a[4], bb[8];
            #pragma unroll
            for (int r = 0; r < 4; r++) a[r] = Es[kk][r*16 + ty];
            #pragma unroll
            for (int c = 0; c < 8; c++) bb[c] = Ws[kk][c*16 + tx];
            #pragma unroll
            for (int r = 0; r < 4; r++)
                #pragma unroll
                for (int c = 0; c < 8; c++) acc[r][c] += a[r] * bb[c];
        }
        __syncthreads();
    }
    #pragma unroll
    for (int c = 0; c < 8; c++) {
        int n = n0 + c*16 + tx;
        float bv = bn1[n];
        #pragma unroll
        for (int r = 0; r < 4; r++) {
            int row = row0 + r*16 + ty;
            g_hn[(size_t)row * H_ + n] = fmaxf(acc[r][c] + bv, 0.f);
        }
    }
}

// ------------------------- K4: filter scores -> sigmoids --------------------
__global__ void score_kernel() {
    int gw = (blockIdx.x * 256 + threadIdx.x) >> 5;   // warp per node-row, 4608 rows
    int lane = threadIdx.x & 31;
    if (gw >= NODE_ROWS) return;
    int b = gw / N_;
    const float* h  = g_hn + (size_t)gw * H_;
    const float* u3 = g_u3 + b * H_;
    const float* u1 = g_u1 + b * H_;
    float d3 = 0.f, d1 = 0.f;
    #pragma unroll
    for (int t = 0; t < 8; t++) {
        int d = lane + t*32;
        float hv = h[d];
        d3 += hv * u3[d];
        d1 += hv * u1[d];
    }
    #pragma unroll
    for (int o = 16; o > 0; o >>= 1) {
        d3 += __shfl_xor_sync(0xffffffffu, d3, o);
        d1 += __shfl_xor_sync(0xffffffffu, d1, o);
    }
    if (lane == 0) {
        g_a1[gw]   = sigmoidf_((d3 + g_c3[b]) * SCALE_);
        g_sig1[gw] = sigmoidf_((d1 + g_c1[b]) * SCALE_);
    }
}

// ------------------------- K5: edge GEMM + fused epilogue -> weit -----------
// Per edge row: h = relu(E@W_e1 + b_e1) [256]; weit = sigmoid((h.v_b + ce_b)*scale)
// BM=144 (1296 = 9*144 exact), BN=128 (2 chunks), BK=32. grid (9, 128), 256 thr.
__global__ __launch_bounds__(256) void edge_kernel(
        const float* __restrict__ edge, const float* __restrict__ We1,
        const float* __restrict__ be1) {
    const int b    = blockIdx.y;
    const int row0 = blockIdx.x * 144;
    const int tid  = threadIdx.x;
    const int tx = tid & 15, ty = tid >> 4;

    __shared__ float Es[32][145];
    __shared__ float Ws[32][128];

    const float* v     = g_v + b * H_;
    const float* Ebase = edge + ((size_t)b * ROWS_PER_B + row0) * DE_;

    float s[9];
    #pragma unroll
    for (int r = 0; r < 9; r++) s[r] = 0.f;

    for (int n0 = 0; n0 < 256; n0 += 128) {
        float acc[9][8];
        #pragma unroll
        for (int r = 0; r < 9; r++)
            #pragma unroll
            for (int c = 0; c < 8; c++) acc[r][c] = 0.f;

        for (int k0 = 0; k0 < DE_; k0 += 32) {
            // E tile 144x32 = 1152 float4
            #pragma unroll
            for (int t = 0; t < 5; t++) {
                int i4 = tid + t*256;
                if (i4 < 1152) {
                    int r = i4 >> 3, c4 = i4 & 7;
                    float4 e = *(const float4*)(Ebase + (size_t)r * DE_ + k0 + c4*4);
                    Es[c4*4+0][r] = e.x; Es[c4*4+1][r] = e.y;
                    Es[c4*4+2][r] = e.z; Es[c4*4+3][r] = e.w;
                }
            }
            // W tile 32x128 = 1024 float4
            #pragma unroll
            for (int t = 0; t < 4; t++) {
                int i4 = tid + t*256;
                int r = i4 >> 5, c4 = i4 & 31;
                *(float4*)(&Ws[r][c4*4]) = *(const float4*)(We1 + (size_t)(k0 + r) * 256 + n0 + c4*4);
            }
            __syncthreads();
            #pragma unroll
            for (int kk = 0; kk < 32; kk++) {
                float a[9], bb[8];
                #pragma unroll
                for (int r = 0; r < 9; r++) a[r] = Es[kk][r*16 + ty];
                #pragma unroll
                for (int c = 0; c < 8; c++) bb[c] = Ws[kk][c*16 + tx];
                #pragma unroll
                for (int r = 0; r < 9; r++)
                    #pragma unroll
                    for (int c = 0; c < 8; c++) acc[r][c] += a[r] * bb[c];
            }
            __syncthreads();
        }
        // fused epilogue: relu(+bias), dot with v
        #pragma unroll
        for (int c = 0; c < 8; c++) {
            int n = n0 + c*16 + tx;
            float bn = be1[n];
            float vn = v[n];
            #pragma unroll
            for (int r = 0; r < 9; r++) {
                float h = acc[r][c] + bn;
                h = fmaxf(h, 0.f);
                s[r] += h * vn;
            }
        }
    }
    // reduce across tx (16 lanes of each half-warp)
    float ce = g_ce[b];
    #pragma unroll
    for (int r = 0; r < 9; r++) {
        float x = s[r];
        x += __shfl_xor_sync(0xffffffffu, x, 8);
        x += __shfl_xor_sync(0xffffffffu, x, 4);
        x += __shfl_xor_sync(0xffffffffu, x, 2);
        x += __shfl_xor_sync(0xffffffffu, x, 1);
        if (tx == 0) {
            int row = row0 + r*16 + ty;
            g_weit[(size_t)b * ROWS_PER_B + row] = sigmoidf_((x + ce) * SCALE_);
        }
    }
}

// ------------------------- K6: attention chain + pooled hidden --------------
__global__ void combine_kernel() {
    int b = blockIdx.x;
    int tid = threadIdx.x;      // 256 threads
    __shared__ float a1s[N_];
    __shared__ float a3s[N_];
    __shared__ float sInv, sS;
    if (tid < N_) a1s[tid] = g_a1[b * N_ + tid];
    __syncthreads();
    if (tid < N_) {
        int j = tid;
        float acc = 0.f;
        const float* w = g_weit + (size_t)b * ROWS_PER_B;
        #pragma unroll
        for (int i = 0; i < N_; i++) acc += a1s[i] * w[i * N_ + j];
        acc = fminf(fmaxf(acc, 0.f), 1.f);
        a3s[j] = acc * g_sig1[b * N_ + j];
    }
    __syncthreads();
    if (tid == 0) {
        float s0 = 0.f;
        #pragma unroll
        for (int j = 0; j < N_; j++) s0 += a3s[j];
        float inv = 1.f / (s0 + 1e-8f);
        sInv = inv;
        sS = s0 * inv;
    }
    __syncthreads();
    // pooled hidden: ph[h] = sum_j an[j] * hn[b,j,h]
    {
        int h = tid;
        float acc = 0.f;
        #pragma unroll
        for (int j = 0; j < N_; j++)
            acc += a3s[j] * g_hn[((size_t)(b * N_ + j)) * H_ + h];
        g_ph[b * H_ + h] = acc * sInv;
    }
    if (tid == 0) g_S[b] = sS;
}

// ------------------------- K7: final GEMV chain -> logits -------------------
__global__ void final_kernel(const float* __restrict__ Wn2, const float* __restrict__ bn2,
                             const float* __restrict__ Wq,  const float* __restrict__ bq,
                             const float* __restrict__ Wc1, const float* __restrict__ bc1,
                             const float* __restrict__ Wc2, const float* __restrict__ bc2,
                             float* __restrict__ out) {
    int b = blockIdx.x;
    int tid = threadIdx.x;      // 256 threads
    __shared__ float ph[H_];
    __shared__ float q0[DV_];
    __shared__ float g[DV_];
    __shared__ float o1[DV_];
    __shared__ float h2[H_];
    ph[tid] = g_ph[b * H_ + tid];
    q0[tid]       = g_q[(b*4 + 0) * DV_ + tid];
    q0[tid + 256] = g_q[(b*4 + 0) * DV_ + tid + 256];
    __syncthreads();
    float S = g_S[b];
    // stage A: pooled (gated by q0)
    for (int d = tid; d < DV_; d += 256) {
        float acc = 0.f;
        for (int h = 0; h < H_; h++) acc += ph[h] * Wn2[(size_t)h * DV_ + d];
        g[d] = (acc + S * bn2[d]) * q0[d];
    }
    __syncthreads();
    // stage B: out = relu(g @ W_q + b_q)
    for (int e = tid; e < DV_; e += 256) {
        float acc = bq[e];
        for (int d = 0; d < DV_; d++) acc += g[d] * Wq[(size_t)d * DV_ + e];
        o1[e] = fmaxf(acc, 0.f);
    }
    __syncthreads();
    // stage C: h2 = relu(out @ W_c1 + b_c1)
    {
        int c = tid;
        float acc = bc1[c];
        for (int e = 0; e < DV_; e++) acc += o1[e] * Wc1[(size_t)e * H_ + c];
        h2[c] = fmaxf(acc, 0.f);
    }
    __syncthreads();
    // stage D: logits
    if (tid < NC_) {
        float acc = bc2[tid];
        for (int c = 0; c < H_; c++) acc += h2[c] * Wc2[(size_t)c * NC_ + tid];
        out[b * NC_ + tid] = acc;
    }
}

// ------------------------- launch ------------------------------------------
extern "C" void kernel_launch(void* const* d_in, const int* in_sizes, int n_in,
                              void* d_out, int out_size) {
    const float* node     = (const float*)d_in[0];
    const float* edge     = (const float*)d_in[1];
    const float* Wn1      = (const float*)d_in[2];
    const float* bn1      = (const float*)d_in[3];
    const float* Wn2      = (const float*)d_in[4];
    const float* bn2      = (const float*)d_in[5];
    const float* We1      = (const float*)d_in[6];
    const float* be1      = (const float*)d_in[7];
    const float* We2      = (const float*)d_in[8];
    const float* be2      = (const float*)d_in[9];
    const float* Wq       = (const float*)d_in[10];
    const float* bq       = (const float*)d_in[11];
    const float* Wc1      = (const float*)d_in[12];
    const float* bc1      = (const float*)d_in[13];
    const float* Wc2      = (const float*)d_in[14];
    const float* bc2      = (const float*)d_in[15];
    const float* word_emb = (const float*)d_in[16];
    // d_in[17] = programs (unused by reference)
    const int* prog_in    = (const int*)d_in[18];
    float* out            = (float*)d_out;

    gather_q_kernel<<<(B_*4*DV_)/256, 256>>>(word_emb, prog_in);
    proj_kernel<<<dim3(B_, 3), 256>>>(Wn2, bn2, We2, be2);
    node_mlp1_kernel<<<dim3(NODE_ROWS/64, 2), 256>>>(node, Wn1, bn1);
    score_kernel<<<NODE_ROWS/8, 256>>>();
    edge_kernel<<<dim3(ROWS_PER_B/144, B_), 256>>>(edge, We1, be1);
    combine_kernel<<<B_, 256>>>();
    final_kernel<<<B_, 256>>>(Wn2, bn2, Wq, bq, Wc1, bc1, Wc2, bc2, out);
}

// round 2
// speedup vs baseline: 1.8529x; 1.8529x over previous
#include <cuda_runtime.h>
#include <math.h>

// Dims (CLEVR-scale, fixed)
#define B_   128
#define N_   36
#define DF_  512
#define DE_  256
#define DV_  512
#define H_   256
#define NC_  28
#define L_   5
#define ROWS_PER_B (N_*N_)          // 1296
#define NODE_ROWS  (B_*N_)          // 4608
#define EDGE_ROWS  (B_*ROWS_PER_B)  // 165888
#define SCALE_ 0.04419417382415922f // 1/sqrt(512)
#define BK_ 16

// ------------------------- device scratch (no cudaMalloc allowed) -----------
__device__ float g_hn[NODE_ROWS * H_];       // relu(node@W_n1+b_n1)
__device__ float g_q[B_ * 4 * DV_];
__device__ float g_u3[B_ * H_];
__device__ float g_u1[B_ * H_];
__device__ float g_v [B_ * H_];
__device__ float g_c3[B_];
__device__ float g_c1[B_];
__device__ float g_ce[B_];
__device__ float g_a1  [NODE_ROWS];
__device__ float g_sig1[NODE_ROWS];
__device__ float g_weit[EDGE_ROWS];          // linear: b*1296 + i*36 + j
__device__ float g_ph[B_ * H_];
__device__ float g_S [B_];

__device__ __forceinline__ float sigmoidf_(float x) { return 1.0f / (1.0f + expf(-x)); }
__device__ __forceinline__ unsigned f2tf32(float x) {
    unsigned u; asm("cvt.rna.tf32.f32 %0, %1;" : "=r"(u) : "f"(x)); return u;
}
__device__ __forceinline__ void mma_tf32(float c[4], const unsigned a[4], const unsigned b[2]) {
    asm volatile("mma.sync.aligned.m16n8k8.row.col.f32.tf32.tf32.f32 "
        "{%0,%1,%2,%3}, {%4,%5,%6,%7}, {%8,%9}, {%0,%1,%2,%3};"
        : "+f"(c[0]), "+f"(c[1]), "+f"(c[2]), "+f"(c[3])
        : "r"(a[0]), "r"(a[1]), "r"(a[2]), "r"(a[3]), "r"(b[0]), "r"(b[1]));
}

// ------------------------- K1: gather q = word_emb[program_inputs] ----------
__global__ void gather_q_kernel(const float* __restrict__ word_emb,
                                const int* __restrict__ prog_in) {
    int idx = blockIdx.x * 256 + threadIdx.x;
    int d = idx & (DV_ - 1);
    int l = (idx >> 9) & 3;
    int b = idx >> 11;
    int w = prog_in[b * L_ + l];
    g_q[idx] = word_emb[(size_t)w * DV_ + d];
}

// ------------------------- K2: per-batch projections u3,u1,v and scalars ----
__global__ void proj_kernel(const float* __restrict__ Wn2, const float* __restrict__ bn2,
                            const float* __restrict__ We2, const float* __restrict__ be2) {
    int b = blockIdx.x;
    int which = blockIdx.y;
    const float* W; const float* bias; const float* q; float* u; float* cptr;
    if (which == 0)      { W = Wn2; bias = bn2; q = g_q + (b*4 + 3)*DV_; u = g_u3 + b*H_; cptr = g_c3 + b; }
    else if (which == 1) { W = Wn2; bias = bn2; q = g_q + (b*4 + 1)*DV_; u = g_u1 + b*H_; cptr = g_c1 + b; }
    else                 { W = We2; bias = be2; q = g_q + (b*4 + 2)*DV_; u = g_v  + b*H_; cptr = g_ce + b; }

    __shared__ float qs[DV_];
    __shared__ float red[256];
    int tid = threadIdx.x;
    qs[tid]       = q[tid];
    qs[tid + 256] = q[tid + 256];
    __syncthreads();

    int warp = tid >> 5, lane = tid & 31;
    for (int h = warp; h < H_; h += 8) {
        float acc = 0.f;
        const float* Wr = W + (size_t)h * DV_;
        #pragma unroll
        for (int t = 0; t < 16; t++) { int d = lane + t*32; acc += Wr[d] * qs[d]; }
        #pragma unroll
        for (int o = 16; o > 0; o >>= 1) acc += __shfl_xor_sync(0xffffffffu, acc, o);
        if (lane == 0) u[h] = acc;
    }
    red[tid] = bias[tid] * qs[tid] + bias[tid + 256] * qs[tid + 256];
    __syncthreads();
    for (int o = 128; o > 0; o >>= 1) { if (tid < o) red[tid] += red[tid + o]; __syncthreads(); }
    if (tid == 0) *cptr = red[0];
}

// ------------------------- K3: node MLP1 via tf32 tensor cores --------------
// hn = relu(node @ W_n1 + b_n1). M=4608, K=512, N=256.
// BM=128, BN=256, BK=16; 512 threads, warp grid 4(M)x4(N), warp tile 32x64.
__global__ __launch_bounds__(512, 1) void node_mma_kernel(
        const float* __restrict__ node, const float* __restrict__ Wn1,
        const float* __restrict__ bn1) {
    __shared__ unsigned As[128][20];
    __shared__ unsigned Bs[BK_][264];
    __shared__ float bs[256];

    const int tid  = threadIdx.x;
    const int warp = tid >> 5, lane = tid & 31;
    const int warpM = warp >> 2, warpN = warp & 3;
    const int g = lane >> 2, kq = lane & 3;
    const int row0 = blockIdx.x * 128;

    if (tid < 256) bs[tid] = bn1[tid];

    float acc[2][8][4];
    #pragma unroll
    for (int mt = 0; mt < 2; mt++)
        #pragma unroll
        for (int nt = 0; nt < 8; nt++)
            #pragma unroll
            for (int c = 0; c < 4; c++) acc[mt][nt][c] = 0.f;

    const int ra = tid >> 2, ca = tid & 3;          // A load coords
    const float* Abase = node + (size_t)row0 * DF_;

    float4 pa;
    float4 pb[2];

    // prefetch stage 0
    {
        pa = *(const float4*)(Abase + (size_t)ra * DF_ + ca*4);
        #pragma unroll
        for (int t = 0; t < 2; t++) {
            int i4 = tid + t*512; int kr = i4 >> 6, c4 = i4 & 63;
            pb[t] = *(const float4*)(Wn1 + (size_t)kr * H_ + c4*4);
        }
    }
    const int S = DF_ / BK_;                          // 32 stages
    for (int s = 0; s < S; s++) {
        // store prefetched regs -> smem (tf32)
        *(uint4*)&As[ra][ca*4] = make_uint4(f2tf32(pa.x), f2tf32(pa.y), f2tf32(pa.z), f2tf32(pa.w));
        #pragma unroll
        for (int t = 0; t < 2; t++) {
            int i4 = tid + t*512; int kr = i4 >> 6, c4 = i4 & 63;
            *(uint4*)&Bs[kr][c4*4] = make_uint4(f2tf32(pb[t].x), f2tf32(pb[t].y), f2tf32(pb[t].z), f2tf32(pb[t].w));
        }
        __syncthreads();
        if (s + 1 < S) {
            int k0 = (s + 1) * BK_;
            pa = *(const float4*)(Abase + (size_t)ra * DF_ + k0 + ca*4);
            #pragma unroll
            for (int t = 0; t < 2; t++) {
                int i4 = tid + t*512; int kr = i4 >> 6, c4 = i4 & 63;
                pb[t] = *(const float4*)(Wn1 + (size_t)(k0 + kr) * H_ + c4*4);
            }
        }
        #pragma unroll
        for (int kk = 0; kk < 2; kk++) {
            unsigned af[2][4], bf[8][2];
            #pragma unroll
            for (int mt = 0; mt < 2; mt++) {
                int r = warpM*32 + mt*16 + g;
                af[mt][0] = As[r    ][kk*8 + kq];
                af[mt][1] = As[r + 8][kk*8 + kq];
                af[mt][2] = As[r    ][kk*8 + kq + 4];
                af[mt][3] = As[r + 8][kk*8 + kq + 4];
            }
            #pragma unroll
            for (int nt = 0; nt < 8; nt++) {
                int n = warpN*64 + nt*8 + g;
                bf[nt][0] = Bs[kk*8 + kq    ][n];
                bf[nt][1] = Bs[kk*8 + kq + 4][n];
            }
            #pragma unroll
            for (int mt = 0; mt < 2; mt++)
                #pragma unroll
                for (int nt = 0; nt < 8; nt++) mma_tf32(acc[mt][nt], af[mt], bf[nt]);
        }
        __syncthreads();
    }
    // epilogue: relu(+bias) -> g_hn (float2 stores)
    #pragma unroll
    for (int mt = 0; mt < 2; mt++) {
        int rA = row0 + warpM*32 + mt*16 + g;
        int rB = rA + 8;
        #pragma unroll
        for (int nt = 0; nt < 8; nt++) {
            int n = warpN*64 + nt*8 + kq*2;
            float b0v = bs[n], b1v = bs[n+1];
            float2 v0 = make_float2(fmaxf(acc[mt][nt][0] + b0v, 0.f), fmaxf(acc[mt][nt][1] + b1v, 0.f));
            float2 v1 = make_float2(fmaxf(acc[mt][nt][2] + b0v, 0.f), fmaxf(acc[mt][nt][3] + b1v, 0.f));
            *(float2*)&g_hn[(size_t)rA * H_ + n] = v0;
            *(float2*)&g_hn[(size_t)rB * H_ + n] = v1;
        }
    }
}

// ------------------------- K4: filter scores -> sigmoids --------------------
__global__ void score_kernel() {
    int gw = (blockIdx.x * 256 + threadIdx.x) >> 5;
    int lane = threadIdx.x & 31;
    if (gw >= NODE_ROWS) return;
    int b = gw / N_;
    const float* h  = g_hn + (size_t)gw * H_;
    const float* u3 = g_u3 + b * H_;
    const float* u1 = g_u1 + b * H_;
    float d3 = 0.f, d1 = 0.f;
    #pragma unroll
    for (int t = 0; t < 8; t++) {
        int d = lane + t*32;
        float hv = h[d];
        d3 += hv * u3[d];
        d1 += hv * u1[d];
    }
    #pragma unroll
    for (int o = 16; o > 0; o >>= 1) {
        d3 += __shfl_xor_sync(0xffffffffu, d3, o);
        d1 += __shfl_xor_sync(0xffffffffu, d1, o);
    }
    if (lane == 0) {
        g_a1[gw]   = sigmoidf_((d3 + g_c3[b]) * SCALE_);
        g_sig1[gw] = sigmoidf_((d1 + g_c1[b]) * SCALE_);
    }
}

// ------------------------- K5: edge GEMM via tf32 tensor cores --------------
// weit = sigmoid((relu(E@We1+be1) . v_b + ce_b)*scale). M=165888, K=256, N=256.
// BM=128, BN=256, BK=16; 512 threads; fused epilogue.
__global__ __launch_bounds__(512, 1) void edge_mma_kernel(
        const float* __restrict__ edge, const float* __restrict__ We1,
        const float* __restrict__ be1) {
    __shared__ unsigned As[128][20];
    __shared__ unsigned Bs[BK_][264];
    __shared__ float s_sh[128];
    __shared__ float bs[256], vs0[256], vs1[256];
    __shared__ float ces[2];

    const int tid  = threadIdx.x;
    const int warp = tid >> 5, lane = tid & 31;
    const int warpM = warp >> 2, warpN = warp & 3;
    const int g = lane >> 2, kq = lane & 3;
    const int row0 = blockIdx.x * 128;

    const int b0 = row0 / ROWS_PER_B;
    const int bn_ = (b0 + 1 < B_) ? b0 + 1 : b0;
    const int split = (b0 + 1) * ROWS_PER_B - row0;   // local rows >= split belong to b0+1

    if (tid < 256) {
        bs[tid]  = be1[tid];
        vs0[tid] = g_v[b0  * H_ + tid];
        vs1[tid] = g_v[bn_ * H_ + tid];
    }
    if (tid < 128) s_sh[tid] = 0.f;
    if (tid == 0) { ces[0] = g_ce[b0]; ces[1] = g_ce[bn_]; }

    float acc[2][8][4];
    #pragma unroll
    for (int mt = 0; mt < 2; mt++)
        #pragma unroll
        for (int nt = 0; nt < 8; nt++)
            #pragma unroll
            for (int c = 0; c < 4; c++) acc[mt][nt][c] = 0.f;

    const int ra = tid >> 2, ca = tid & 3;
    const float* Abase = edge + (size_t)row0 * DE_;

    float4 pa;
    float4 pb[2];
    {
        pa = *(const float4*)(Abase + (size_t)ra * DE_ + ca*4);
        #pragma unroll
        for (int t = 0; t < 2; t++) {
            int i4 = tid + t*512; int kr = i4 >> 6, c4 = i4 & 63;
            pb[t] = *(const float4*)(We1 + (size_t)kr * 256 + c4*4);
        }
    }
    const int S = DE_ / BK_;                          // 16 stages
    for (int s = 0; s < S; s++) {
        *(uint4*)&As[ra][ca*4] = make_uint4(f2tf32(pa.x), f2tf32(pa.y), f2tf32(pa.z), f2tf32(pa.w));
        #pragma unroll
        for (int t = 0; t < 2; t++) {
            int i4 = tid + t*512; int kr = i4 >> 6, c4 = i4 & 63;
            *(uint4*)&Bs[kr][c4*4] = make_uint4(f2tf32(pb[t].x), f2tf32(pb[t].y), f2tf32(pb[t].z), f2tf32(pb[t].w));
        }
        __syncthreads();
        if (s + 1 < S) {
            int k0 = (s + 1) * BK_;
            pa = *(const float4*)(Abase + (size_t)ra * DE_ + k0 + ca*4);
            #pragma unroll
            for (int t = 0; t < 2; t++) {
                int i4 = tid + t*512; int kr = i4 >> 6, c4 = i4 & 63;
                pb[t] = *(const float4*)(We1 + (size_t)(k0 + kr) * 256 + c4*4);
            }
        }
        #pragma unroll
        for (int kk = 0; kk < 2; kk++) {
            unsigned af[2][4], bf[8][2];
            #pragma unroll
            for (int mt = 0; mt < 2; mt++) {
                int r = warpM*32 + mt*16 + g;
                af[mt][0] = As[r    ][kk*8 + kq];
                af[mt][1] = As[r + 8][kk*8 + kq];
                af[mt][2] = As[r    ][kk*8 + kq + 4];
                af[mt][3] = As[r + 8][kk*8 + kq + 4];
            }
            #pragma unroll
            for (int nt = 0; nt < 8; nt++) {
                int n = warpN*64 + nt*8 + g;
                bf[nt][0] = Bs[kk*8 + kq    ][n];
                bf[nt][1] = Bs[kk*8 + kq + 4][n];
            }
            #pragma unroll
            for (int mt = 0; mt < 2; mt++)
                #pragma unroll
                for (int nt = 0; nt < 8; nt++) mma_tf32(acc[mt][nt], af[mt], bf[nt]);
        }
        __syncthreads();
    }
    // fused epilogue: bias+relu, dot with v_b, reduce, sigmoid
    #pragma unroll
    for (int mt = 0; mt < 2; mt++) {
        int rA = warpM*32 + mt*16 + g;
        int rB = rA + 8;
        const float* vA = (rA < split) ? vs0 : vs1;
        const float* vB = (rB < split) ? vs0 : vs1;
        float pA = 0.f, pB = 0.f;
        #pragma unroll
        for (int nt = 0; nt < 8; nt++) {
            int n = warpN*64 + nt*8 + kq*2;
            float b0v = bs[n], b1v = bs[n+1];
            pA += fmaxf(acc[mt][nt][0] + b0v, 0.f) * vA[n]
                + fmaxf(acc[mt][nt][1] + b1v, 0.f) * vA[n+1];
            pB += fmaxf(acc[mt][nt][2] + b0v, 0.f) * vB[n]
                + fmaxf(acc[mt][nt][3] + b1v, 0.f) * vB[n+1];
        }
        pA += __shfl_xor_sync(0xffffffffu, pA, 1);
        pA += __shfl_xor_sync(0xffffffffu, pA, 2);
        pB += __shfl_xor_sync(0xffffffffu, pB, 1);
        pB += __shfl_xor_sync(0xffffffffu, pB, 2);
        if (kq == 0) {
            atomicAdd(&s_sh[rA], pA);
            atomicAdd(&s_sh[rB], pB);
        }
    }
    __syncthreads();
    if (tid < 128) {
        float ce = (tid < split) ? ces[0] : ces[1];
        g_weit[row0 + tid] = sigmoidf_((s_sh[tid] + ce) * SCALE_);
    }
}

// ------------------------- K6: attention chain + pooled hidden --------------
__global__ void combine_kernel() {
    int b = blockIdx.x;
    int tid = threadIdx.x;      // 256 threads
    __shared__ float a1s[N_];
    __shared__ float a3s[N_];
    __shared__ float sInv, sS;
    if (tid < N_) a1s[tid] = g_a1[b * N_ + tid];
    __syncthreads();
    if (tid < N_) {
        int j = tid;
        float acc = 0.f;
        const float* w = g_weit + (size_t)b * ROWS_PER_B;
        #pragma unroll
        for (int i = 0; i < N_; i++) acc += a1s[i] * w[i * N_ + j];
        acc = fminf(fmaxf(acc, 0.f), 1.f);
        a3s[j] = acc * g_sig1[b * N_ + j];
    }
    __syncthreads();
    if (tid == 0) {
        float s0 = 0.f;
        #pragma unroll
        for (int j = 0; j < N_; j++) s0 += a3s[j];
        float inv = 1.f / (s0 + 1e-8f);
        sInv = inv;
        sS = s0 * inv;
    }
    __syncthreads();
    {
        int h = tid;
        float acc = 0.f;
        #pragma unroll
        for (int j = 0; j < N_; j++)
            acc += a3s[j] * g_hn[((size_t)(b * N_ + j)) * H_ + h];
        g_ph[b * H_ + h] = acc * sInv;
    }
    if (tid == 0) g_S[b] = sS;
}

// ------------------------- K7: final GEMV chain -> logits -------------------
__global__ void final_kernel(const float* __restrict__ Wn2, const float* __restrict__ bn2,
                             const float* __restrict__ Wq,  const float* __restrict__ bq,
                             const float* __restrict__ Wc1, const float* __restrict__ bc1,
                             const float* __restrict__ Wc2, const float* __restrict__ bc2,
                             float* __restrict__ out) {
    int b = blockIdx.x;
    int tid = threadIdx.x;      // 256 threads
    __shared__ float ph[H_];
    __shared__ float q0[DV_];
    __shared__ float g[DV_];
    __shared__ float o1[DV_];
    __shared__ float h2[H_];
    ph[tid] = g_ph[b * H_ + tid];
    q0[tid]       = g_q[(b*4 + 0) * DV_ + tid];
    q0[tid + 256] = g_q[(b*4 + 0) * DV_ + tid + 256];
    __syncthreads();
    float S = g_S[b];
    for (int d = tid; d < DV_; d += 256) {
        float acc = 0.f;
        for (int h = 0; h < H_; h++) acc += ph[h] * Wn2[(size_t)h * DV_ + d];
        g[d] = (acc + S * bn2[d]) * q0[d];
    }
    __syncthreads();
    for (int e = tid; e < DV_; e += 256) {
        float acc = bq[e];
        for (int d = 0; d < DV_; d++) acc += g[d] * Wq[(size_t)d * DV_ + e];
        o1[e] = fmaxf(acc, 0.f);
    }
    __syncthreads();
    {
        int c = tid;
        float acc = bc1[c];
        for (int e = 0; e < DV_; e++) acc += o1[e] * Wc1[(size_t)e * H_ + c];
        h2[c] = fmaxf(acc, 0.f);
    }
    __syncthreads();
    if (tid < NC_) {
        float acc = bc2[tid];
        for (int c = 0; c < H_; c++) acc += h2[c] * Wc2[(size_t)c * NC_ + tid];
        out[b * NC_ + tid] = acc;
    }
}

// ------------------------- launch ------------------------------------------
extern "C" void kernel_launch(void* const* d_in, const int* in_sizes, int n_in,
                              void* d_out, int out_size) {
    const float* node     = (const float*)d_in[0];
    const float* edge     = (const float*)d_in[1];
    const float* Wn1      = (const float*)d_in[2];
    const float* bn1      = (const float*)d_in[3];
    const float* Wn2      = (const float*)d_in[4];
    const float* bn2      = (const float*)d_in[5];
    const float* We1      = (const float*)d_in[6];
    const float* be1      = (const float*)d_in[7];
    const float* We2      = (const float*)d_in[8];
    const float* be2      = (const float*)d_in[9];
    const float* Wq       = (const float*)d_in[10];
    const float* bq       = (const float*)d_in[11];
    const float* Wc1      = (const float*)d_in[12];
    const float* bc1      = (const float*)d_in[13];
    const float* Wc2      = (const float*)d_in[14];
    const float* bc2      = (const float*)d_in[15];
    const float* word_emb = (const float*)d_in[16];
    const int* prog_in    = (const int*)d_in[18];
    float* out            = (float*)d_out;

    gather_q_kernel<<<(B_*4*DV_)/256, 256>>>(word_emb, prog_in);
    proj_kernel<<<dim3(B_, 3), 256>>>(Wn2, bn2, We2, be2);
    node_mma_kernel<<<NODE_ROWS/128, 512>>>(node, Wn1, bn1);
    score_kernel<<<NODE_ROWS/8, 256>>>();
    edge_mma_kernel<<<EDGE_ROWS/128, 512>>>(edge, We1, be1);
    combine_kernel<<<B_, 256>>>();
    final_kernel<<<B_, 256>>>(Wn2, bn2, Wq, bq, Wc1, bc1, Wc2, bc2, out);
}

// round 4
// speedup vs baseline: 2.4092x; 1.3002x over previous
#include <cuda_runtime.h>
#include <math.h>
#include <stdint.h>

// Dims (CLEVR-scale, fixed)
#define B_   128
#define N_   36
#define DF_  512
#define DE_  256
#define DV_  512
#define H_   256
#define NC_  28
#define L_   5
#define ROWS_PER_B (N_*N_)          // 1296
#define NODE_ROWS  (B_*N_)          // 4608
#define EDGE_ROWS  (B_*ROWS_PER_B)  // 165888
#define SCALE_ 0.04419417382415922f // 1/sqrt(512)
#define BK_ 16

// Feature gate: tcgen05 exists only in arch-specific (sm_103a / sm_100a) passes.
#if defined(__CUDA_ARCH_FEAT_SM103_ALL) || defined(__CUDA_ARCH_FEAT_SM100_ALL) || defined(__CUDA_ARCH_FEAT_SM101_ALL)
#define HAS_TC 1
#else
#define HAS_TC 0
#endif

// ------------------------- device scratch (no cudaMalloc allowed) -----------
__device__ float g_hn[NODE_ROWS * H_];
__device__ float g_q[B_ * 4 * DV_];
__device__ float g_u3[B_ * H_];
__device__ float g_u1[B_ * H_];
__device__ float g_v [B_ * H_];
__device__ float g_c3[B_];
__device__ float g_c1[B_];
__device__ float g_ce[B_];
__device__ float g_a1  [NODE_ROWS];
__device__ float g_sig1[NODE_ROWS];
__device__ float g_weit[EDGE_ROWS];
__device__ float g_ph[B_ * H_];
__device__ float g_S [B_];
__device__ float g_We1T[H_ * DE_];   // We1 transposed: [n][k]

__device__ __forceinline__ float sigmoidf_(float x) { return 1.0f / (1.0f + expf(-x)); }
__device__ __forceinline__ unsigned f2tf32(float x) {
    unsigned u; asm("cvt.rna.tf32.f32 %0, %1;" : "=r"(u) : "f"(x)); return u;
}
__device__ __forceinline__ void mma_tf32(float c[4], const unsigned a[4], const unsigned b[2]) {
    asm volatile("mma.sync.aligned.m16n8k8.row.col.f32.tf32.tf32.f32 "
        "{%0,%1,%2,%3}, {%4,%5,%6,%7}, {%8,%9}, {%0,%1,%2,%3};"
        : "+f"(c[0]), "+f"(c[1]), "+f"(c[2]), "+f"(c[3])
        : "r"(a[0]), "r"(a[1]), "r"(a[2]), "r"(a[3]), "r"(b[0]), "r"(b[1]));
}

// ------------------------- tcgen05 helpers (only instantiated when used) ----
__device__ __forceinline__ uint32_t smem_u32(const void* p) {
    uint32_t a;
    asm("{ .reg .u64 t; cvta.to.shared.u64 t, %1; cvt.u32.u64 %0, t; }" : "=r"(a) : "l"(p));
    return a;
}
__device__ __forceinline__ uint32_t elect_one_pred() {
    uint32_t pred;
    asm volatile("{\n\t.reg .pred p;\n\telect.sync _|p, 0xFFFFFFFF;\n\t"
                 "selp.b32 %0, 1, 0, p;\n\t}" : "=r"(pred));
    return pred;
}
static __device__ constexpr uint64_t SMEM_DESC_BASE_SW128 =
    (uint64_t(2)  << 61) | (uint64_t(1) << 46) | (uint64_t(64) << 32) | (uint64_t(1) << 16);
__device__ __forceinline__ uint64_t make_desc(uint32_t addr) {
    return SMEM_DESC_BASE_SW128 | ((uint64_t)(addr >> 4) & 0x3FFF);
}
// tf32 SS idesc: dtype=F32(1<<4), a/btype=TF32(2<<7,2<<10), N/8<<17, M/16<<24
#define EDGE_IDESC 0x8400910u

#if HAS_TC
__device__ __forceinline__ void tc_mma_tf32_ss(uint32_t d_tmem, uint64_t a_desc,
                                               uint64_t b_desc, uint32_t idesc, bool accum) {
    uint32_t en = accum ? 1u : 0u;
    asm volatile(
        "{\n\t.reg .pred p;\n\t"
        "setp.ne.u32 p, %5, 0;\n\t"
        "tcgen05.mma.cta_group::1.kind::tf32 [%0], %1, %2, %3, {%4, %4, %4, %4}, p;\n\t}"
        :: "r"(d_tmem), "l"(a_desc), "l"(b_desc), "r"(idesc), "r"(0u), "r"(en)
        : "memory");
}
#define TC_ALLOC(smem_addr, n) \
    asm volatile("tcgen05.alloc.cta_group::1.sync.aligned.shared::cta.b32 [%0], %1;" \
                 :: "r"((uint32_t)(smem_addr)), "r"((uint32_t)(n)) : "memory")
#define TC_DEALLOC(tmem, n) \
    asm volatile("tcgen05.dealloc.cta_group::1.sync.aligned.b32 %0, %1;" :: "r"(tmem), "r"((uint32_t)(n)))
#define TC_RELINQ() asm volatile("tcgen05.relinquish_alloc_permit.cta_group::1.sync.aligned;")
#define TC_COMMIT(mbar) \
    asm volatile("tcgen05.commit.cta_group::1.mbarrier::arrive::one.shared::cluster.b64 [%0];" \
                 :: "r"((uint32_t)(mbar)) : "memory")
#define TC_FENCE_AFTER()  asm volatile("tcgen05.fence::after_thread_sync;" ::: "memory")
#define TC_WAIT_LD()      asm volatile("tcgen05.wait::ld.sync.aligned;" ::: "memory")
#define MBAR_INIT(addr, cnt) \
    asm volatile("mbarrier.init.shared.b64 [%0], %1;" :: "r"((uint32_t)(addr)), "r"((uint32_t)(cnt)) : "memory")
#define MBAR_INVAL(addr) \
    asm volatile("mbarrier.inval.shared.b64 [%0];" :: "r"((uint32_t)(addr)) : "memory")
#define FENCE_PROXY_ASYNC() asm volatile("fence.proxy.async.shared::cta;" ::: "memory")
__device__ __forceinline__ void mbar_wait_parity(uint32_t addr, uint32_t parity) {
    asm volatile(
        "{\n\t.reg .pred P1;\n\t"
        "WAIT_%=:\n\t"
        "mbarrier.try_wait.parity.acquire.cta.shared::cta.b64 P1, [%0], %1, 0x989680;\n\t"
        "@P1 bra.uni DONE_%=;\n\t"
        "bra.uni WAIT_%=;\n\t"
        "DONE_%=:\n\t}"
        :: "r"(addr), "r"(parity) : "memory");
}
#define LDTM_X32(r, addr) \
    asm volatile( \
        "tcgen05.ld.sync.aligned.32x32b.x32.b32 " \
        "{%0, %1, %2, %3, %4, %5, %6, %7, " \
        " %8, %9, %10, %11, %12, %13, %14, %15, " \
        " %16, %17, %18, %19, %20, %21, %22, %23, " \
        " %24, %25, %26, %27, %28, %29, %30, %31}, [%32];" \
        : "=r"((r)[0]),  "=r"((r)[1]),  "=r"((r)[2]),  "=r"((r)[3]), \
          "=r"((r)[4]),  "=r"((r)[5]),  "=r"((r)[6]),  "=r"((r)[7]), \
          "=r"((r)[8]),  "=r"((r)[9]),  "=r"((r)[10]), "=r"((r)[11]), \
          "=r"((r)[12]), "=r"((r)[13]), "=r"((r)[14]), "=r"((r)[15]), \
          "=r"((r)[16]), "=r"((r)[17]), "=r"((r)[18]), "=r"((r)[19]), \
          "=r"((r)[20]), "=r"((r)[21]), "=r"((r)[22]), "=r"((r)[23]), \
          "=r"((r)[24]), "=r"((r)[25]), "=r"((r)[26]), "=r"((r)[27]), \
          "=r"((r)[28]), "=r"((r)[29]), "=r"((r)[30]), "=r"((r)[31]) \
        : "r"(addr))
#endif // HAS_TC

// ------------------------- K0: transpose We1 --------------------------------
__global__ void transpose_We1_kernel(const float* __restrict__ We1) {
    __shared__ float t[32][33];
    int bx = blockIdx.x * 32;   // n block
    int by = blockIdx.y * 32;   // k block
    t[threadIdx.y][threadIdx.x] = We1[(size_t)(by + threadIdx.y) * H_ + bx + threadIdx.x];
    __syncthreads();
    g_We1T[(size_t)(bx + threadIdx.y) * DE_ + by + threadIdx.x] = t[threadIdx.x][threadIdx.y];
}

// ------------------------- K1: gather q -------------------------------------
__global__ void gather_q_kernel(const float* __restrict__ word_emb,
                                const int* __restrict__ prog_in) {
    int idx = blockIdx.x * 256 + threadIdx.x;
    int d = idx & (DV_ - 1);
    int l = (idx >> 9) & 3;
    int b = idx >> 11;
    int w = prog_in[b * L_ + l];
    g_q[idx] = word_emb[(size_t)w * DV_ + d];
}

// ------------------------- K2: per-batch projections -------------------------
__global__ void proj_kernel(const float* __restrict__ Wn2, const float* __restrict__ bn2,
                            const float* __restrict__ We2, const float* __restrict__ be2) {
    int b = blockIdx.x;
    int which = blockIdx.y;
    const float* W; const float* bias; const float* q; float* u; float* cptr;
    if (which == 0)      { W = Wn2; bias = bn2; q = g_q + (b*4 + 3)*DV_; u = g_u3 + b*H_; cptr = g_c3 + b; }
    else if (which == 1) { W = Wn2; bias = bn2; q = g_q + (b*4 + 1)*DV_; u = g_u1 + b*H_; cptr = g_c1 + b; }
    else                 { W = We2; bias = be2; q = g_q + (b*4 + 2)*DV_; u = g_v  + b*H_; cptr = g_ce + b; }

    __shared__ float qs[DV_];
    __shared__ float red[256];
    int tid = threadIdx.x;
    qs[tid]       = q[tid];
    qs[tid + 256] = q[tid + 256];
    __syncthreads();

    int warp = tid >> 5, lane = tid & 31;
    for (int h = warp; h < H_; h += 8) {
        float acc = 0.f;
        const float* Wr = W + (size_t)h * DV_;
        #pragma unroll
        for (int t = 0; t < 16; t++) { int d = lane + t*32; acc += Wr[d] * qs[d]; }
        #pragma unroll
        for (int o = 16; o > 0; o >>= 1) acc += __shfl_xor_sync(0xffffffffu, acc, o);
        if (lane == 0) u[h] = acc;
    }
    red[tid] = bias[tid] * qs[tid] + bias[tid + 256] * qs[tid + 256];
    __syncthreads();
    for (int o = 128; o > 0; o >>= 1) { if (tid < o) red[tid] += red[tid + o]; __syncthreads(); }
    if (tid == 0) *cptr = red[0];
}

// ------------------------- K3: node MLP1 (tf32 mma.sync) --------------------
__global__ __launch_bounds__(512, 1) void node_mma_kernel(
        const float* __restrict__ node, const float* __restrict__ Wn1,
        const float* __restrict__ bn1) {
    __shared__ unsigned As[128][20];
    __shared__ unsigned Bs[BK_][264];
    __shared__ float bs[256];

    const int tid  = threadIdx.x;
    const int warp = tid >> 5, lane = tid & 31;
    const int warpM = warp >> 2, warpN = warp & 3;
    const int g = lane >> 2, kq = lane & 3;
    const int row0 = blockIdx.x * 128;

    if (tid < 256) bs[tid] = bn1[tid];

    float acc[2][8][4];
    #pragma unroll
    for (int mt = 0; mt < 2; mt++)
        #pragma unroll
        for (int nt = 0; nt < 8; nt++)
            #pragma unroll
            for (int c = 0; c < 4; c++) acc[mt][nt][c] = 0.f;

    const int ra = tid >> 2, ca = tid & 3;
    const float* Abase = node + (size_t)row0 * DF_;

    float4 pa;
    float4 pb[2];
    {
        pa = *(const float4*)(Abase + (size_t)ra * DF_ + ca*4);
        #pragma unroll
        for (int t = 0; t < 2; t++) {
            int i4 = tid + t*512; int kr = i4 >> 6, c4 = i4 & 63;
            pb[t] = *(const float4*)(Wn1 + (size_t)kr * H_ + c4*4);
        }
    }
    const int S = DF_ / BK_;
    for (int s = 0; s < S; s++) {
        *(uint4*)&As[ra][ca*4] = make_uint4(f2tf32(pa.x), f2tf32(pa.y), f2tf32(pa.z), f2tf32(pa.w));
        #pragma unroll
        for (int t = 0; t < 2; t++) {
            int i4 = tid + t*512; int kr = i4 >> 6, c4 = i4 & 63;
            *(uint4*)&Bs[kr][c4*4] = make_uint4(f2tf32(pb[t].x), f2tf32(pb[t].y), f2tf32(pb[t].z), f2tf32(pb[t].w));
        }
        __syncthreads();
        if (s + 1 < S) {
            int k0 = (s + 1) * BK_;
            pa = *(const float4*)(Abase + (size_t)ra * DF_ + k0 + ca*4);
            #pragma unroll
            for (int t = 0; t < 2; t++) {
                int i4 = tid + t*512; int kr = i4 >> 6, c4 = i4 & 63;
                pb[t] = *(const float4*)(Wn1 + (size_t)(k0 + kr) * H_ + c4*4);
            }
        }
        #pragma unroll
        for (int kk = 0; kk < 2; kk++) {
            unsigned af[2][4], bf[8][2];
            #pragma unroll
            for (int mt = 0; mt < 2; mt++) {
                int r = warpM*32 + mt*16 + g;
                af[mt][0] = As[r    ][kk*8 + kq];
                af[mt][1] = As[r + 8][kk*8 + kq];
                af[mt][2] = As[r    ][kk*8 + kq + 4];
                af[mt][3] = As[r + 8][kk*8 + kq + 4];
            }
            #pragma unroll
            for (int nt = 0; nt < 8; nt++) {
                int n = warpN*64 + nt*8 + g;
                bf[nt][0] = Bs[kk*8 + kq    ][n];
                bf[nt][1] = Bs[kk*8 + kq + 4][n];
            }
            #pragma unroll
            for (int mt = 0; mt < 2; mt++)
                #pragma unroll
                for (int nt = 0; nt < 8; nt++) mma_tf32(acc[mt][nt], af[mt], bf[nt]);
        }
        __syncthreads();
    }
    #pragma unroll
    for (int mt = 0; mt < 2; mt++) {
        int rA = row0 + warpM*32 + mt*16 + g;
        int rB = rA + 8;
        #pragma unroll
        for (int nt = 0; nt < 8; nt++) {
            int n = warpN*64 + nt*8 + kq*2;
            float b0v = bs[n], b1v = bs[n+1];
            float2 v0 = make_float2(fmaxf(acc[mt][nt][0] + b0v, 0.f), fmaxf(acc[mt][nt][1] + b1v, 0.f));
            float2 v1 = make_float2(fmaxf(acc[mt][nt][2] + b0v, 0.f), fmaxf(acc[mt][nt][3] + b1v, 0.f));
            *(float2*)&g_hn[(size_t)rA * H_ + n] = v0;
            *(float2*)&g_hn[(size_t)rB * H_ + n] = v1;
        }
    }
}

// ------------------------- K4: filter scores --------------------------------
__global__ void score_kernel() {
    int gw = (blockIdx.x * 256 + threadIdx.x) >> 5;
    int lane = threadIdx.x & 31;
    if (gw >= NODE_ROWS) return;
    int b = gw / N_;
    const float* h  = g_hn + (size_t)gw * H_;
    const float* u3 = g_u3 + b * H_;
    const float* u1 = g_u1 + b * H_;
    float d3 = 0.f, d1 = 0.f;
    #pragma unroll
    for (int t = 0; t < 8; t++) {
        int d = lane + t*32;
        float hv = h[d];
        d3 += hv * u3[d];
        d1 += hv * u1[d];
    }
    #pragma unroll
    for (int o = 16; o > 0; o >>= 1) {
        d3 += __shfl_xor_sync(0xffffffffu, d3, o);
        d1 += __shfl_xor_sync(0xffffffffu, d1, o);
    }
    if (lane == 0) {
        g_a1[gw]   = sigmoidf_((d3 + g_c3[b]) * SCALE_);
        g_sig1[gw] = sigmoidf_((d1 + g_c1[b]) * SCALE_);
    }
}

// ------------------------- K5a: edge GEMM via tcgen05 (feature pass only) ---
#define EDGE_SMEM_DYN (1024 + 2*16384 + 2*32768)
__global__ __launch_bounds__(256, 1)
void edge_tc_kernel(const float* __restrict__ edge, const float* __restrict__ be1) {
#if HAS_TC
    extern __shared__ char dsm[];
    __shared__ uint32_t sh_tmem;
    __shared__ uint64_t sh_mbar[2];
    __shared__ float bs[256], vs0[256], vs1[256];
    __shared__ float s_part[256];
    __shared__ float ces[2];

    const int tid = threadIdx.x;
    const int warp = tid >> 5, lane = tid & 31;
    const int row0 = blockIdx.x * 128;

    const int b0 = row0 / ROWS_PER_B;
    const int bn_ = (b0 + 1 < B_) ? b0 + 1 : b0;
    const int split = (b0 + 1) * ROWS_PER_B - row0;

    uint32_t dbase = smem_u32(dsm);
    uint32_t aligned = (dbase + 1023u) & ~1023u;
    char* smbase = dsm + (aligned - dbase);
    const uint32_t Aoff[2] = {0u, 16384u};
    const uint32_t Boff[2] = {32768u, 65536u};

    if (warp == 0) { TC_ALLOC(smem_u32(&sh_tmem), 256); TC_RELINQ(); }
    if (tid == 0) {
        MBAR_INIT(smem_u32(&sh_mbar[0]), 1);
        MBAR_INIT(smem_u32(&sh_mbar[1]), 1);
        ces[0] = g_ce[b0]; ces[1] = g_ce[bn_];
    }
    bs[tid]  = be1[tid];
    vs0[tid] = g_v[b0  * H_ + tid];
    vs1[tid] = g_v[bn_ * H_ + tid];
    __syncthreads();

    const uint32_t tmem = sh_tmem;
    const uint32_t mb0 = smem_u32(&sh_mbar[0]);
    const uint32_t mb1 = smem_u32(&sh_mbar[1]);
    const float* Abase = edge + (size_t)row0 * DE_;

    #pragma unroll 1
    for (int c = 0; c < 8; c++) {
        const int buf = c & 1;
        if (c >= 2) {
            uint32_t u = (uint32_t)(c - 2) >> 1;
            mbar_wait_parity(buf ? mb1 : mb0, u & 1u);
        }
        const int k0 = c * 32;
        char* Ab = smbase + Aoff[buf];
        #pragma unroll
        for (int t = 0; t < 4; t++) {
            int i4 = tid + t*256;
            int r = i4 >> 3, c4 = i4 & 7;
            float4 v = *(const float4*)(Abase + (size_t)r * DE_ + k0 + c4*4);
            uint32_t byte = (uint32_t)(r*128 + c4*16);
            uint32_t sw = byte ^ ((byte >> 3) & 0x70u);
            *(uint4*)(Ab + sw) = make_uint4(f2tf32(v.x), f2tf32(v.y), f2tf32(v.z), f2tf32(v.w));
        }
        char* Bb = smbase + Boff[buf];
        #pragma unroll
        for (int t = 0; t < 8; t++) {
            int i4 = tid + t*256;
            int n = i4 >> 3, c4 = i4 & 7;
            float4 v = *(const float4*)(g_We1T + (size_t)n * DE_ + k0 + c4*4);
            uint32_t byte = (uint32_t)(n*128 + c4*16);
            uint32_t sw = byte ^ ((byte >> 3) & 0x70u);
            *(uint4*)(Bb + sw) = make_uint4(f2tf32(v.x), f2tf32(v.y), f2tf32(v.z), f2tf32(v.w));
        }
        FENCE_PROXY_ASYNC();
        __syncthreads();
        if (warp == 0) {
            if (elect_one_pred()) {
                uint64_t ad = make_desc(aligned + Aoff[buf]);
                uint64_t bd = make_desc(aligned + Boff[buf]);
                #pragma unroll
                for (int s = 0; s < 4; s++)
                    tc_mma_tf32_ss(tmem, ad + 2*s, bd + 2*s, EDGE_IDESC, (c > 0) || (s > 0));
                TC_COMMIT(buf ? mb1 : mb0);
            }
        }
    }
    mbar_wait_parity(mb0, 1u);
    mbar_wait_parity(mb1, 1u);
    TC_FENCE_AFTER();

    {
        const int half = warp >> 2;
        const int r = (warp & 3) * 32 + lane;
        const float* vrow = (r < split) ? vs0 : vs1;
        float s = 0.f;
        #pragma unroll
        for (int j = 0; j < 4; j++) {
            uint32_t d[32];
            int cbase = half*128 + j*32;
            LDTM_X32(d, tmem + cbase);
            TC_WAIT_LD();
            #pragma unroll
            for (int cc = 0; cc < 32; cc++) {
                int col = cbase + cc;
                float h = fmaxf(__uint_as_float(d[cc]) + bs[col], 0.f);
                s += h * vrow[col];
            }
        }
        s_part[half*128 + r] = s;
    }
    __syncthreads();
    if (tid < 128) {
        float tot = s_part[tid] + s_part[128 + tid];
        float ce = (tid < split) ? ces[0] : ces[1];
        g_weit[row0 + tid] = sigmoidf_((tot + ce) * SCALE_);
    }
    __syncthreads();
    if (tid == 0) { MBAR_INVAL(mb0); MBAR_INVAL(mb1); }
    if (warp == 0) TC_DEALLOC(tmem, 256);
#else
    // no tcgen05 in this pass: no-op (edge_mma_kernel does the work)
    (void)edge; (void)be1;
#endif
}

// ------------------------- K5b: edge GEMM via mma.sync (base pass only) -----
__global__ __launch_bounds__(512, 1) void edge_mma_kernel(
        const float* __restrict__ edge, const float* __restrict__ We1,
        const float* __restrict__ be1) {
#if !HAS_TC
    __shared__ unsigned As[128][20];
    __shared__ unsigned Bs[BK_][264];
    __shared__ float s_sh[128];
    __shared__ float bs[256], vs0[256], vs1[256];
    __shared__ float ces[2];

    const int tid  = threadIdx.x;
    const int warp = tid >> 5, lane = tid & 31;
    const int warpM = warp >> 2, warpN = warp & 3;
    const int g = lane >> 2, kq = lane & 3;
    const int row0 = blockIdx.x * 128;

    const int b0 = row0 / ROWS_PER_B;
    const int bn_ = (b0 + 1 < B_) ? b0 + 1 : b0;
    const int split = (b0 + 1) * ROWS_PER_B - row0;

    if (tid < 256) {
        bs[tid]  = be1[tid];
        vs0[tid] = g_v[b0  * H_ + tid];
        vs1[tid] = g_v[bn_ * H_ + tid];
    }
    if (tid < 128) s_sh[tid] = 0.f;
    if (tid == 0) { ces[0] = g_ce[b0]; ces[1] = g_ce[bn_]; }

    float acc[2][8][4];
    #pragma unroll
    for (int mt = 0; mt < 2; mt++)
        #pragma unroll
        for (int nt = 0; nt < 8; nt++)
            #pragma unroll
            for (int c = 0; c < 4; c++) acc[mt][nt][c] = 0.f;

    const int ra = tid >> 2, ca = tid & 3;
    const float* Abase = edge + (size_t)row0 * DE_;

    float4 pa;
    float4 pb[2];
    {
        pa = *(const float4*)(Abase + (size_t)ra * DE_ + ca*4);
        #pragma unroll
        for (int t = 0; t < 2; t++) {
            int i4 = tid + t*512; int kr = i4 >> 6, c4 = i4 & 63;
            pb[t] = *(const float4*)(We1 + (size_t)kr * 256 + c4*4);
        }
    }
    const int S = DE_ / BK_;
    for (int s = 0; s < S; s++) {
        *(uint4*)&As[ra][ca*4] = make_uint4(f2tf32(pa.x), f2tf32(pa.y), f2tf32(pa.z), f2tf32(pa.w));
        #pragma unroll
        for (int t = 0; t < 2; t++) {
            int i4 = tid + t*512; int kr = i4 >> 6, c4 = i4 & 63;
            *(uint4*)&Bs[kr][c4*4] = make_uint4(f2tf32(pb[t].x), f2tf32(pb[t].y), f2tf32(pb[t].z), f2tf32(pb[t].w));
        }
        __syncthreads();
        if (s + 1 < S) {
            int k0 = (s + 1) * BK_;
            pa = *(const float4*)(Abase + (size_t)ra * DE_ + k0 + ca*4);
            #pragma unroll
            for (int t = 0; t < 2; t++) {
                int i4 = tid + t*512; int kr = i4 >> 6, c4 = i4 & 63;
                pb[t] = *(const float4*)(We1 + (size_t)(k0 + kr) * 256 + c4*4);
            }
        }
        #pragma unroll
        for (int kk = 0; kk < 2; kk++) {
            unsigned af[2][4], bf[8][2];
            #pragma unroll
            for (int mt = 0; mt < 2; mt++) {
                int r = warpM*32 + mt*16 + g;
                af[mt][0] = As[r    ][kk*8 + kq];
                af[mt][1] = As[r + 8][kk*8 + kq];
                af[mt][2] = As[r    ][kk*8 + kq + 4];
                af[mt][3] = As[r + 8][kk*8 + kq + 4];
            }
            #pragma unroll
            for (int nt = 0; nt < 8; nt++) {
                int n = warpN*64 + nt*8 + g;
                bf[nt][0] = Bs[kk*8 + kq    ][n];
                bf[nt][1] = Bs[kk*8 + kq + 4][n];
            }
            #pragma unroll
            for (int mt = 0; mt < 2; mt++)
                #pragma unroll
                for (int nt = 0; nt < 8; nt++) mma_tf32(acc[mt][nt], af[mt], bf[nt]);
        }
        __syncthreads();
    }
    #pragma unroll
    for (int mt = 0; mt < 2; mt++) {
        int rA = warpM*32 + mt*16 + g;
        int rB = rA + 8;
        const float* vA = (rA < split) ? vs0 : vs1;
        const float* vB = (rB < split) ? vs0 : vs1;
        float pA = 0.f, pB = 0.f;
        #pragma unroll
        for (int nt = 0; nt < 8; nt++) {
            int n = warpN*64 + nt*8 + kq*2;
            float b0v = bs[n], b1v = bs[n+1];
            pA += fmaxf(acc[mt][nt][0] + b0v, 0.f) * vA[n]
                + fmaxf(acc[mt][nt][1] + b1v, 0.f) * vA[n+1];
            pB += fmaxf(acc[mt][nt][2] + b0v, 0.f) * vB[n]
                + fmaxf(acc[mt][nt][3] + b1v, 0.f) * vB[n+1];
        }
        pA += __shfl_xor_sync(0xffffffffu, pA, 1);
        pA += __shfl_xor_sync(0xffffffffu, pA, 2);
        pB += __shfl_xor_sync(0xffffffffu, pB, 1);
        pB += __shfl_xor_sync(0xffffffffu, pB, 2);
        if (kq == 0) {
            atomicAdd(&s_sh[rA], pA);
            atomicAdd(&s_sh[rB], pB);
        }
    }
    __syncthreads();
    if (tid < 128) {
        float ce = (tid < split) ? ces[0] : ces[1];
        g_weit[row0 + tid] = sigmoidf_((s_sh[tid] + ce) * SCALE_);
    }
#else
    (void)edge; (void)We1; (void)be1;   // tcgen05 pass: no-op
#endif
}

// ------------------------- K6: attention chain + pooled hidden --------------
__global__ void combine_kernel() {
    int b = blockIdx.x;
    int tid = threadIdx.x;
    __shared__ float a1s[N_];
    __shared__ float a3s[N_];
    __shared__ float sInv, sS;
    if (tid < N_) a1s[tid] = g_a1[b * N_ + tid];
    __syncthreads();
    if (tid < N_) {
        int j = tid;
        float acc = 0.f;
        const float* w = g_weit + (size_t)b * ROWS_PER_B;
        #pragma unroll
        for (int i = 0; i < N_; i++) acc += a1s[i] * w[i * N_ + j];
        acc = fminf(fmaxf(acc, 0.f), 1.f);
        a3s[j] = acc * g_sig1[b * N_ + j];
    }
    __syncthreads();
    if (tid == 0) {
        float s0 = 0.f;
        #pragma unroll
        for (int j = 0; j < N_; j++) s0 += a3s[j];
        float inv = 1.f / (s0 + 1e-8f);
        sInv = inv;
        sS = s0 * inv;
    }
    __syncthreads();
    {
        int h = tid;
        float acc = 0.f;
        #pragma unroll
        for (int j = 0; j < N_; j++)
            acc += a3s[j] * g_hn[((size_t)(b * N_ + j)) * H_ + h];
        g_ph[b * H_ + h] = acc * sInv;
    }
    if (tid == 0) g_S[b] = sS;
}

// ------------------------- K7: final GEMV chain -> logits -------------------
__global__ void final_kernel(const float* __restrict__ Wn2, const float* __restrict__ bn2,
                             const float* __restrict__ Wq,  const float* __restrict__ bq,
                             const float* __restrict__ Wc1, const float* __restrict__ bc1,
                             const float* __restrict__ Wc2, const float* __restrict__ bc2,
                             float* __restrict__ out) {
    int b = blockIdx.x;
    int tid = threadIdx.x;
    __shared__ float ph[H_];
    __shared__ float q0[DV_];
    __shared__ float g[DV_];
    __shared__ float o1[DV_];
    __shared__ float h2[H_];
    ph[tid] = g_ph[b * H_ + tid];
    q0[tid]       = g_q[(b*4 + 0) * DV_ + tid];
    q0[tid + 256] = g_q[(b*4 + 0) * DV_ + tid + 256];
    __syncthreads();
    float S = g_S[b];
    for (int d = tid; d < DV_; d += 256) {
        float acc = 0.f;
        for (int h = 0; h < H_; h++) acc += ph[h] * Wn2[(size_t)h * DV_ + d];
        g[d] = (acc + S * bn2[d]) * q0[d];
    }
    __syncthreads();
    for (int e = tid; e < DV_; e += 256) {
        float acc = bq[e];
        for (int d = 0; d < DV_; d++) acc += g[d] * Wq[(size_t)d * DV_ + e];
        o1[e] = fmaxf(acc, 0.f);
    }
    __syncthreads();
    {
        int c = tid;
        float acc = bc1[c];
        for (int e = 0; e < DV_; e++) acc += o1[e] * Wc1[(size_t)e * H_ + c];
        h2[c] = fmaxf(acc, 0.f);
    }
    __syncthreads();
    if (tid < NC_) {
        float acc = bc2[tid];
        for (int c = 0; c < H_; c++) acc += h2[c] * Wc2[(size_t)c * NC_ + tid];
        out[b * NC_ + tid] = acc;
    }
}

// ------------------------- launch ------------------------------------------
extern "C" void kernel_launch(void* const* d_in, const int* in_sizes, int n_in,
                              void* d_out, int out_size) {
    const float* node     = (const float*)d_in[0];
    const float* edge     = (const float*)d_in[1];
    const float* Wn1      = (const float*)d_in[2];
    const float* bn1      = (const float*)d_in[3];
    const float* Wn2      = (const float*)d_in[4];
    const float* bn2      = (const float*)d_in[5];
    const float* We1      = (const float*)d_in[6];
    const float* be1      = (const float*)d_in[7];
    const float* We2      = (const float*)d_in[8];
    const float* be2      = (const float*)d_in[9];
    const float* Wq       = (const float*)d_in[10];
    const float* bq       = (const float*)d_in[11];
    const float* Wc1      = (const float*)d_in[12];
    const float* bc1      = (const float*)d_in[13];
    const float* Wc2      = (const float*)d_in[14];
    const float* bc2      = (const float*)d_in[15];
    const float* word_emb = (const float*)d_in[16];
    const int* prog_in    = (const int*)d_in[18];
    float* out            = (float*)d_out;

    cudaFuncSetAttribute(edge_tc_kernel,
                         cudaFuncAttributeMaxDynamicSharedMemorySize, EDGE_SMEM_DYN);

    transpose_We1_kernel<<<dim3(8, 8), dim3(32, 32)>>>(We1);
    gather_q_kernel<<<(B_*4*DV_)/256, 256>>>(word_emb, prog_in);
    proj_kernel<<<dim3(B_, 3), 256>>>(Wn2, bn2, We2, be2);
    node_mma_kernel<<<NODE_ROWS/128, 512>>>(node, Wn1, bn1);
    score_kernel<<<NODE_ROWS/8, 256>>>();
    edge_tc_kernel<<<EDGE_ROWS/128, 256, EDGE_SMEM_DYN>>>(edge, be1);
    edge_mma_kernel<<<EDGE_ROWS/128, 512>>>(edge, We1, be1);
    combine_kernel<<<B_, 256>>>();
    final_kernel<<<B_, 256>>>(Wn2, bn2, Wq, bq, Wc1, bc1, Wc2, bc2, out);
}